// round 4
// baseline (speedup 1.0000x reference)
#include <cuda_runtime.h>
#include <math.h>

// ---------------- problem constants ----------------
constexpr int Bsz = 32, T = 1024, D = 256, NH = 2, DK = 128, DH = 1024, L = 4;
constexpr int M_ALL = Bsz * T;          // 32768 rows
constexpr int TPAD  = T + 8;            // conv1 halo (4 each side)
constexpr float EPS = 1e-5f;

// ---------------- device scratch (static, no allocations) ----------------
__device__ float g_h     [ (long)M_ALL * D ];          // ln1 output
__device__ float g_qkv   [ (long)M_ALL * 3 * D ];      // qkv projections
__device__ float g_scores[ (long)Bsz * NH * T * T ];   // attention scores (268MB)
__device__ float g_attno [ (long)M_ALL * D ];          // attention output (heads merged)
__device__ float g_hpad  [ (long)Bsz * TPAD * D ];     // ln2 output, 4-row zero halo per batch
__device__ float g_hid   [ (long)M_ALL * DH ];         // conv1 output (relu'd)
__device__ float g_wt1   [ (long)L * DH * D * 9 ];     // conv1 weights repacked [l][o][kk*D+i]
__device__ float g_nonpad[ M_ALL ];                    // (seq != 0) as float

// ---------------- packed fp32x2 helpers (FFMA2) ----------------
__device__ __forceinline__ void ffma2(unsigned long long& d,
                                      unsigned long long a,
                                      unsigned long long b) {
    asm("fma.rn.f32x2 %0, %1, %2, %0;" : "+l"(d) : "l"(a), "l"(b));
}
__device__ __forceinline__ unsigned long long pack2(float x) {
    unsigned long long r;
    asm("mov.b64 %0, {%1, %1};" : "=l"(r) : "f"(x));
    return r;
}

// ---------------- reductions ----------------
__device__ __forceinline__ float blockReduceSum(float v) {
    __shared__ float sh[8];
    int lane = threadIdx.x & 31, w = threadIdx.x >> 5;
    #pragma unroll
    for (int o = 16; o; o >>= 1) v += __shfl_xor_sync(0xffffffffu, v, o);
    if (!lane) sh[w] = v;
    __syncthreads();
    if (w == 0) {
        v = (lane < 8) ? sh[lane] : 0.f;
        #pragma unroll
        for (int o = 4; o; o >>= 1) v += __shfl_xor_sync(0xffffffffu, v, o);
        if (!lane) sh[0] = v;
    }
    __syncthreads();
    float r = sh[0];
    __syncthreads();
    return r;
}

__device__ __forceinline__ float blockReduceMax(float v) {
    __shared__ float sh[8];
    int lane = threadIdx.x & 31, w = threadIdx.x >> 5;
    #pragma unroll
    for (int o = 16; o; o >>= 1) v = fmaxf(v, __shfl_xor_sync(0xffffffffu, v, o));
    if (!lane) sh[w] = v;
    __syncthreads();
    if (w == 0) {
        v = (lane < 8) ? sh[lane] : -3.0e38f;
        #pragma unroll
        for (int o = 4; o; o >>= 1) v = fmaxf(v, __shfl_xor_sync(0xffffffffu, v, o));
        if (!lane) sh[0] = v;
    }
    __syncthreads();
    float r = sh[0];
    __syncthreads();
    return r;
}

// ---------------- small kernels ----------------
__global__ void embed_k(const int* __restrict__ seq, const int* __restrict__ pos,
                        const float* __restrict__ we, const float* __restrict__ pe,
                        float* __restrict__ x) {
    int r = blockIdx.x, d = threadIdx.x;
    int s = seq[r], p = pos[r];
    x[(long)r * D + d] = we[(long)s * D + d] + pe[(long)p * D + d];
    if (d == 0) g_nonpad[r] = (s != 0) ? 1.f : 0.f;
}

// padmode 0: out row r at out+r*D ; padmode 1: out row at hpad interior (+4 rows)
__global__ void ln_k(const float* __restrict__ x, const float* __restrict__ g,
                     const float* __restrict__ bb, float* __restrict__ out, int padmode) {
    int r = blockIdx.x, d = threadIdx.x;
    float v = x[(long)r * D + d];
    float mean = blockReduceSum(v) * (1.f / D);
    float c = v - mean;
    float var = blockReduceSum(c * c) * (1.f / D);
    float y = c * rsqrtf(var + EPS) * g[d] + bb[d];
    long o;
    if (padmode) {
        int b = r / T, t = r % T;
        o = ((long)b * TPAD + t + 4) * D + d;
    } else {
        o = (long)r * D + d;
    }
    out[o] = y;
}

__global__ void zero_halo_k() {
    int idx = blockIdx.x * blockDim.x + threadIdx.x;   // Bsz*8*D = 65536
    int b = idx / (8 * D);
    int rr = (idx / D) % 8;
    int d = idx % D;
    int t = (rr < 4) ? rr : (T + 4 + rr - 4);
    g_hpad[((long)b * TPAD + t) * D + d] = 0.f;
}

__global__ void repack_w1_k(const float* __restrict__ w) {
    long i = (long)blockIdx.x * blockDim.x + threadIdx.x;
    const long total = (long)L * DH * D * 9;
    if (i >= total) return;
    long base = i / (D * 9);        // l*DH + o
    int p = (int)(i % (D * 9));     // kk*D + ii
    int kk = p / D, ii = p % D;
    g_wt1[i] = w[base * (D * 9) + (long)ii * 9 + kk];
}

__global__ void softmax_k(float* __restrict__ sc, const int* __restrict__ seq) {
    long row = blockIdx.x;                 // B*NH*T rows
    int b = (int)(row / ((long)NH * T));
    float* p = sc + row * T;
    const int* sq = seq + (long)b * T;
    const float scale = 0.08838834764831845f;  // 1/sqrt(128)
    int tid = threadIdx.x;
    float vals[4];
    float mx = -3.0e38f;
    #pragma unroll
    for (int q = 0; q < 4; q++) {
        int k = tid + q * 256;
        float v = (sq[k] == 0) ? -3.0e38f : p[k] * scale;
        vals[q] = v;
        mx = fmaxf(mx, v);
    }
    float M = blockReduceMax(mx);
    float s = 0.f;
    #pragma unroll
    for (int q = 0; q < 4; q++) {
        float e = __expf(vals[q] - M);
        vals[q] = e;
        s += e;
    }
    float S = blockReduceSum(s);
    float inv = 1.f / S;
    #pragma unroll
    for (int q = 0; q < 4; q++) p[tid + q * 256] = vals[q] * inv;
}

__global__ void copy_np_k(float* __restrict__ out) {
    int i = blockIdx.x * blockDim.x + threadIdx.x;
    if (i < M_ALL) out[i] = g_nonpad[i];
}

// ---------------- generic batched SGEMM (double-buffered, FFMA2 core) --------
// C[m,n] = sum_k A[m,k] * (BT ? B[n,k] : B[k,n])
// epilogue: +bias[n], relu, +resid (C-shaped), *mask[m]
// batch z: b = z/H, h = z%H with per-(b,h) pointer strides.
// Requirements: M,N multiples of 128; K multiple of 8 and >= 16; ld* multiples of 4.
template <bool BT>
__global__ __launch_bounds__(256)
void sgemm_k(const float* __restrict__ A, int lda, long aSb, long aSh,
             const float* __restrict__ Bm, int ldb, long bSb, long bSh,
             float* __restrict__ C, int ldc, long cSb, long cSh,
             int K, int H,
             const float* __restrict__ bias,
             const float* __restrict__ resid,
             const float* __restrict__ mask,
             int relu) {
    int z = blockIdx.z;
    int zb = z / H, zh = z % H;
    A  += (long)zb * aSb + (long)zh * aSh;
    Bm += (long)zb * bSb + (long)zh * bSh;
    C  += (long)zb * cSb + (long)zh * cSh;
    if (resid) resid += (long)zb * cSb + (long)zh * cSh;

    __shared__ float As[2][8][128];
    __shared__ float Bs[2][8][128];

    int tid = threadIdx.x;
    int m0 = blockIdx.x * 128, n0 = blockIdx.y * 128;

    int lm  = tid >> 1;            // 0..127
    int lk  = (tid & 1) * 4;       // 0 or 4
    int lkb = tid >> 5;            // 0..7   (NN B loads)
    int lnb = (tid & 31) * 4;      // 0..124

    int tx = tid & 15, ty = tid >> 4;

    // packed accumulators: 8 m-rows x 4 n-pairs
    unsigned long long acc[8][4];
    #pragma unroll
    for (int i = 0; i < 8; i++)
        #pragma unroll
        for (int j = 0; j < 4; j++) acc[i][j] = 0ull;

    // prologue: load first K-tile into buffer 0
    {
        float4 av = *(const float4*)(A + (long)(m0 + lm) * lda + lk);
        As[0][lk + 0][lm] = av.x; As[0][lk + 1][lm] = av.y;
        As[0][lk + 2][lm] = av.z; As[0][lk + 3][lm] = av.w;
        if (BT) {
            float4 bv = *(const float4*)(Bm + (long)(n0 + lm) * ldb + lk);
            Bs[0][lk + 0][lm] = bv.x; Bs[0][lk + 1][lm] = bv.y;
            Bs[0][lk + 2][lm] = bv.z; Bs[0][lk + 3][lm] = bv.w;
        } else {
            float4 bv = *(const float4*)(Bm + (long)lkb * ldb + n0 + lnb);
            *(float4*)&Bs[0][lkb][lnb] = bv;
        }
    }
    __syncthreads();

    int buf = 0;
    for (int k0 = 0; k0 < K; k0 += 8) {
        // issue next tile's global loads early (into registers)
        float4 av, bv;
        bool more = (k0 + 8) < K;
        if (more) {
            av = *(const float4*)(A + (long)(m0 + lm) * lda + k0 + 8 + lk);
            if (BT) bv = *(const float4*)(Bm + (long)(n0 + lm) * ldb + k0 + 8 + lk);
            else    bv = *(const float4*)(Bm + (long)(k0 + 8 + lkb) * ldb + n0 + lnb);
        }
        // compute on current buffer (packed f32x2 FMAs)
        #pragma unroll
        for (int kk = 0; kk < 8; kk++) {
            float a8[8];
            *(float4*)(a8)     = *(const float4*)&As[buf][kk][ty * 8];
            *(float4*)(a8 + 4) = *(const float4*)&As[buf][kk][ty * 8 + 4];
            // B pairs read directly as 64-bit packed values (16B-aligned)
            unsigned long long bb[4];
            {
                ulonglong2 b01 = *(const ulonglong2*)&Bs[buf][kk][tx * 8];
                ulonglong2 b23 = *(const ulonglong2*)&Bs[buf][kk][tx * 8 + 4];
                bb[0] = b01.x; bb[1] = b01.y; bb[2] = b23.x; bb[3] = b23.y;
            }
            #pragma unroll
            for (int i = 0; i < 8; i++) {
                unsigned long long aa = pack2(a8[i]);
                #pragma unroll
                for (int j = 0; j < 4; j++)
                    ffma2(acc[i][j], aa, bb[j]);
            }
        }
        // store next tile into the other buffer
        if (more) {
            int nb = buf ^ 1;
            As[nb][lk + 0][lm] = av.x; As[nb][lk + 1][lm] = av.y;
            As[nb][lk + 2][lm] = av.z; As[nb][lk + 3][lm] = av.w;
            if (BT) {
                Bs[nb][lk + 0][lm] = bv.x; Bs[nb][lk + 1][lm] = bv.y;
                Bs[nb][lk + 2][lm] = bv.z; Bs[nb][lk + 3][lm] = bv.w;
            } else {
                *(float4*)&Bs[nb][lkb][lnb] = bv;
            }
            __syncthreads();
            buf = nb;
        }
    }

    #pragma unroll
    for (int i = 0; i < 8; i++) {
        int m = m0 + ty * 8 + i;
        float mk = mask ? mask[m] : 1.f;
        #pragma unroll
        for (int j = 0; j < 4; j++) {
            float2 p2 = *reinterpret_cast<float2*>(&acc[i][j]);
            float vv[2] = {p2.x, p2.y};
            #pragma unroll
            for (int h = 0; h < 2; h++) {
                int n = n0 + tx * 8 + j * 2 + h;
                float v = vv[h];
                if (bias) v += bias[n];
                if (relu) v = fmaxf(v, 0.f);
                if (resid) v += resid[(long)m * ldc + n];
                v *= mk;
                C[(long)m * ldc + n] = v;
            }
        }
    }
}

// ---------------- host orchestration ----------------
extern "C" void kernel_launch(void* const* d_in, const int* in_sizes, int n_in,
                              void* d_out, int out_size) {
    const int*   src_seq  = (const int*)  d_in[0];
    const int*   src_pos  = (const int*)  d_in[1];
    const float* word_emb = (const float*)d_in[2];
    const float* pos_emb  = (const float*)d_in[3];
    const float* qkv_w    = (const float*)d_in[4];
    const float* qkv_b    = (const float*)d_in[5];
    const float* fc_w     = (const float*)d_in[6];
    const float* fc_b     = (const float*)d_in[7];
    const float* ln1_g    = (const float*)d_in[8];
    const float* ln1_b    = (const float*)d_in[9];
    const float* conv1_w  = (const float*)d_in[10];
    const float* conv1_b  = (const float*)d_in[11];
    const float* conv2_w  = (const float*)d_in[12];
    const float* conv2_b  = (const float*)d_in[13];
    const float* ln2_g    = (const float*)d_in[14];
    const float* ln2_b    = (const float*)d_in[15];

    float* x = (float*)d_out;   // residual stream lives in d_out

    float *p_h, *p_qkv, *p_sc, *p_ao, *p_hpad, *p_hid, *p_wt1, *p_np;
    cudaGetSymbolAddress((void**)&p_h,    g_h);
    cudaGetSymbolAddress((void**)&p_qkv,  g_qkv);
    cudaGetSymbolAddress((void**)&p_sc,   g_scores);
    cudaGetSymbolAddress((void**)&p_ao,   g_attno);
    cudaGetSymbolAddress((void**)&p_hpad, g_hpad);
    cudaGetSymbolAddress((void**)&p_hid,  g_hid);
    cudaGetSymbolAddress((void**)&p_wt1,  g_wt1);
    cudaGetSymbolAddress((void**)&p_np,   g_nonpad);

    // one-time-per-call prep
    zero_halo_k<<<(Bsz * 8 * D) / 256, 256>>>();
    {
        long total = (long)L * DH * D * 9;
        repack_w1_k<<<(int)((total + 255) / 256), 256>>>(conv1_w);
    }
    embed_k<<<M_ALL, D>>>(src_seq, src_pos, word_emb, pos_emb, x);

    const long S_qkvB = (long)T * 3 * D;   // per-batch stride in qkv
    for (int l = 0; l < L; l++) {
        // ---- attention sublayer ----
        ln_k<<<M_ALL, D>>>(x, ln1_g + l * D, ln1_b + l * D, p_h, 0);

        // qkv: [32768,256] x [768,256]^T -> [32768,768]
        sgemm_k<true><<<dim3(M_ALL / 128, (3 * D) / 128, 1), 256>>>(
            p_h, D, 0, 0,
            qkv_w + (long)l * 3 * D * D, D, 0, 0,
            p_qkv, 3 * D, 0, 0,
            D, 1, qkv_b + l * 3 * D, nullptr, nullptr, 0);

        // scores: per (b,h): Q[1024,128] x K^T -> [1024,1024]
        sgemm_k<true><<<dim3(T / 128, T / 128, Bsz * NH), 256>>>(
            p_qkv,           3 * D, S_qkvB, DK,        // Q
            p_qkv + D,       3 * D, S_qkvB, DK,        // K
            p_sc, T, (long)NH * T * T, (long)T * T,
            DK, NH, nullptr, nullptr, nullptr, 0);

        softmax_k<<<Bsz * NH * T, 256>>>(p_sc, src_seq);

        // attn out: P[1024,1024] x V[1024,128] -> [1024,128]  (NN)
        sgemm_k<false><<<dim3(T / 128, DK / 128, Bsz * NH), 256>>>(
            p_sc, T, (long)NH * T * T, (long)T * T,
            p_qkv + 2 * D, 3 * D, S_qkvB, DK,          // V
            p_ao, D, (long)T * D, DK,
            T, NH, nullptr, nullptr, nullptr, 0);

        // fc + residual + pad-mask -> x
        sgemm_k<true><<<dim3(M_ALL / 128, D / 128, 1), 256>>>(
            p_ao, D, 0, 0,
            fc_w + (long)l * D * D, D, 0, 0,
            x, D, 0, 0,
            D, 1, fc_b + l * D, x, p_np, 0);

        // ---- conv FFN sublayer ----
        ln_k<<<M_ALL, D>>>(x, ln2_g + l * D, ln2_b + l * D, p_hpad, 1);

        // conv1 as NT GEMM: per batch A=hpad[b] (lda=D, overlapping rows), K=2304
        sgemm_k<true><<<dim3(T / 128, DH / 128, Bsz), 256>>>(
            p_hpad, D, (long)TPAD * D, 0,
            p_wt1 + (long)l * DH * D * 9, D * 9, 0, 0,
            p_hid, DH, (long)T * DH, 0,
            D * 9, 1, conv1_b + l * DH, nullptr, nullptr, 1 /*relu*/);

        // conv2 (k=1) + residual + pad-mask -> x
        sgemm_k<true><<<dim3(M_ALL / 128, D / 128, 1), 256>>>(
            p_hid, DH, 0, 0,
            conv2_w + (long)l * D * DH, DH, 0, 0,
            x, D, 0, 0,
            DH, 1, conv2_b + l * D, x, p_np, 0);
    }

    // second output of the reference tuple: non_pad [B,T,1]
    if (out_size >= M_ALL * D + M_ALL) {
        copy_np_k<<<M_ALL / 256, 256>>>((float*)d_out + (long)M_ALL * D);
    }
}

// round 6
// speedup vs baseline: 2.5169x; 2.5169x over previous
#include <cuda_runtime.h>
#include <cuda_bf16.h>
#include <cstdint>
#include <math.h>

// ---------------- problem constants ----------------
constexpr int Bsz = 32, T = 1024, D = 256, NH = 2, DK = 128, DH = 1024, L = 4;
constexpr int M_ALL = Bsz * T;          // 32768 rows
constexpr int TPAD  = T + 8;            // conv1 halo (4 each side)
constexpr int BH    = Bsz * NH;         // 64
constexpr float EPS = 1e-5f;

// plane strides (elements)
constexpr long S_HCAT = (long)M_ALL * D;
constexpr long S_QC   = (long)BH * T * DK;
constexpr long S_PC   = (long)BH * T * T;
constexpr long S_AOC  = (long)M_ALL * D;
constexpr long S_HPC  = (long)Bsz * TPAD * D;
constexpr long S_HIDC = (long)M_ALL * DH;
constexpr long S_WQKV = (long)L * 3 * D * D;
constexpr long S_WFC  = (long)L * D * D;
constexpr long S_W1   = (long)L * DH * D * 9;
constexpr long S_W2   = (long)L * D * DH;

// ---------------- device scratch ----------------
__device__ __nv_bfloat16 g_hcat [2 * S_HCAT];
__device__ float         g_qkvf [(long)M_ALL * 3 * D];
__device__ __nv_bfloat16 g_qc   [2 * S_QC];
__device__ __nv_bfloat16 g_kc   [2 * S_QC];
__device__ __nv_bfloat16 g_vc   [2 * S_QC];   // transposed [bh][d][t]
__device__ float         g_scf  [(long)BH * T * T];
__device__ __nv_bfloat16 g_pc   [2 * S_PC];
__device__ __nv_bfloat16 g_aoc  [2 * S_AOC];
__device__ __nv_bfloat16 g_hpc  [2 * S_HPC];
__device__ __nv_bfloat16 g_hidc [2 * S_HIDC];
__device__ __nv_bfloat16 g_wqkvc[2 * S_WQKV];
__device__ __nv_bfloat16 g_wfcc [2 * S_WFC];
__device__ __nv_bfloat16 g_w1c  [2 * S_W1];
__device__ __nv_bfloat16 g_w2c  [2 * S_W2];
__device__ float         g_nonpad[M_ALL];

// ---------------- mma/ldmatrix helpers (portable sm_80+ ISA) ----------------
__device__ __forceinline__ uint32_t smem_u32(const void* p) {
    uint32_t a;
    asm("{ .reg .u64 t; cvta.to.shared.u64 t, %1; cvt.u32.u64 %0, t; }" : "=r"(a) : "l"(p));
    return a;
}
__device__ __forceinline__ void ldm4(uint32_t* r, uint32_t addr) {
    asm volatile("ldmatrix.sync.aligned.m8n8.x4.shared.b16 {%0,%1,%2,%3},[%4];"
                 : "=r"(r[0]), "=r"(r[1]), "=r"(r[2]), "=r"(r[3]) : "r"(addr));
}
__device__ __forceinline__ void mma16816(float* c, const uint32_t* a, const uint32_t* b) {
    asm volatile("mma.sync.aligned.m16n8k16.row.col.f32.bf16.bf16.f32 "
                 "{%0,%1,%2,%3},{%4,%5,%6,%7},{%8,%9},{%0,%1,%2,%3};"
                 : "+f"(c[0]), "+f"(c[1]), "+f"(c[2]), "+f"(c[3])
                 : "r"(a[0]), "r"(a[1]), "r"(a[2]), "r"(a[3]), "r"(b[0]), "r"(b[1]));
}

// ---------------- reductions ----------------
__device__ __forceinline__ float warpSum(float v) {
    #pragma unroll
    for (int o = 16; o; o >>= 1) v += __shfl_xor_sync(0xffffffffu, v, o);
    return v;
}
__device__ __forceinline__ float blockReduceSum(float v) {
    __shared__ float sh[8];
    int lane = threadIdx.x & 31, w = threadIdx.x >> 5;
    v = warpSum(v);
    if (!lane) sh[w] = v;
    __syncthreads();
    if (w == 0) {
        v = (lane < 8) ? sh[lane] : 0.f;
        #pragma unroll
        for (int o = 4; o; o >>= 1) v += __shfl_xor_sync(0xffffffffu, v, o);
        if (!lane) sh[0] = v;
    }
    __syncthreads();
    float r = sh[0];
    __syncthreads();
    return r;
}
__device__ __forceinline__ float blockReduceMax(float v) {
    __shared__ float sh[8];
    int lane = threadIdx.x & 31, w = threadIdx.x >> 5;
    #pragma unroll
    for (int o = 16; o; o >>= 1) v = fmaxf(v, __shfl_xor_sync(0xffffffffu, v, o));
    if (!lane) sh[w] = v;
    __syncthreads();
    if (w == 0) {
        v = (lane < 8) ? sh[lane] : -3.0e38f;
        #pragma unroll
        for (int o = 4; o; o >>= 1) v = fmaxf(v, __shfl_xor_sync(0xffffffffu, v, o));
        if (!lane) sh[0] = v;
    }
    __syncthreads();
    float r = sh[0];
    __syncthreads();
    return r;
}

__device__ __forceinline__ void split_bf(float v, __nv_bfloat16& h, __nv_bfloat16& l) {
    h = __float2bfloat16(v);
    l = __float2bfloat16(v - __bfloat162float(h));
}
__device__ __forceinline__ uint32_t pack_bf2(__nv_bfloat16 a, __nv_bfloat16 b) {
    __nv_bfloat162 t; t.x = a; t.y = b;
    return *reinterpret_cast<uint32_t*>(&t);
}

// ---------------- small kernels ----------------
__global__ void embed_k(const int* __restrict__ seq, const int* __restrict__ pos,
                        const float* __restrict__ we, const float* __restrict__ pe,
                        float* __restrict__ x) {
    int r = blockIdx.x, d = threadIdx.x;
    int s = seq[r], p = pos[r];
    x[(long)r * D + d] = we[(long)s * D + d] + pe[(long)p * D + d];
    if (d == 0) g_nonpad[r] = (s != 0) ? 1.f : 0.f;
}

__global__ void ln_cat_k(const float* __restrict__ x, const float* __restrict__ g,
                         const float* __restrict__ bb, __nv_bfloat16* __restrict__ out,
                         long S, int padmode) {
    int wid = threadIdx.x >> 5, lane = threadIdx.x & 31;
    long r = (long)blockIdx.x * 8 + wid;
    const float4* px = (const float4*)(x + r * D);
    float4 u = px[lane * 2], w = px[lane * 2 + 1];
    float vals[8] = {u.x, u.y, u.z, u.w, w.x, w.y, w.z, w.w};
    float s = 0.f;
    #pragma unroll
    for (int j = 0; j < 8; j++) s += vals[j];
    s = warpSum(s);
    float mean = s * (1.f / D);
    float q = 0.f;
    #pragma unroll
    for (int j = 0; j < 8; j++) { vals[j] -= mean; q += vals[j] * vals[j]; }
    q = warpSum(q);
    float rstd = rsqrtf(q * (1.f / D) + EPS);
    int col = lane * 8;
    const float4* pg = (const float4*)(g + col);
    const float4* pb = (const float4*)(bb + col);
    float4 g0 = pg[0], g1 = pg[1], b0 = pb[0], b1 = pb[1];
    float gg[8] = {g0.x, g0.y, g0.z, g0.w, g1.x, g1.y, g1.z, g1.w};
    float bbv[8] = {b0.x, b0.y, b0.z, b0.w, b1.x, b1.y, b1.z, b1.w};
    uint32_t hi[4], lo[4];
    #pragma unroll
    for (int j = 0; j < 4; j++) {
        float y0 = vals[2 * j] * rstd * gg[2 * j] + bbv[2 * j];
        float y1 = vals[2 * j + 1] * rstd * gg[2 * j + 1] + bbv[2 * j + 1];
        __nv_bfloat16 h0, l0, h1, l1;
        split_bf(y0, h0, l0); split_bf(y1, h1, l1);
        hi[j] = pack_bf2(h0, h1); lo[j] = pack_bf2(l0, l1);
    }
    long orow;
    if (padmode) { long b = r / T, t = r % T; orow = b * TPAD + t + 4; }
    else orow = r;
    long ob = orow * D + col;
    *(uint4*)(out + ob)      = *(uint4*)hi;
    *(uint4*)(out + S + ob)  = *(uint4*)lo;
}

__global__ void zero_halo_k(__nv_bfloat16* __restrict__ hp, long S) {
    int idx = blockIdx.x * blockDim.x + threadIdx.x;
    int b = idx / (8 * D);
    int rr = (idx / D) % 8;
    int d = idx % D;
    int t = (rr < 4) ? rr : (T + 4 + rr - 4);
    long o = ((long)b * TPAD + t) * D + d;
    hp[o] = __float2bfloat16(0.f);
    hp[S + o] = __float2bfloat16(0.f);
}

__global__ void cvt_w_k(const float* __restrict__ w, __nv_bfloat16* __restrict__ out,
                        long S, long n) {
    long i = (long)blockIdx.x * blockDim.x + threadIdx.x;
    if (i >= n) return;
    __nv_bfloat16 h, l; split_bf(w[i], h, l);
    out[i] = h; out[S + i] = l;
}

__global__ void cvt_w1_k(const float* __restrict__ w, __nv_bfloat16* __restrict__ out, long S) {
    long i = (long)blockIdx.x * blockDim.x + threadIdx.x;
    const long total = S_W1;
    if (i >= total) return;
    long base = i / (D * 9);
    int p = (int)(i % (D * 9));
    int kk = p / D, ii = p % D;
    __nv_bfloat16 h, l; split_bf(w[base * (D * 9) + (long)ii * 9 + kk], h, l);
    out[i] = h; out[S + i] = l;
}

__global__ void cvt_qkv_k(const float* __restrict__ qkv,
                          __nv_bfloat16* __restrict__ qc, __nv_bfloat16* __restrict__ kc,
                          __nv_bfloat16* __restrict__ vc, long S) {
    long idx = (long)blockIdx.x * blockDim.x + threadIdx.x;   // M_ALL*64
    long r = idx >> 6; int c4 = (int)(idx & 63);
    int b = (int)(r / T), t = (int)(r % T);
    int c = c4 * 4; int h = c >> 7; int d = c & 127;
    long src = r * (3 * D);
    float4 q = *(const float4*)(qkv + src + c);
    float4 k = *(const float4*)(qkv + src + D + c);
    float4 v = *(const float4*)(qkv + src + 2 * D + c);
    long bh = (long)b * NH + h;
    long qdst = (bh * T + t) * DK + d;
    {
        float a[4] = {q.x, q.y, q.z, q.w};
        __nv_bfloat16 hh[4], ll[4];
        #pragma unroll
        for (int j = 0; j < 4; j++) split_bf(a[j], hh[j], ll[j]);
        uint32_t hu[2] = {pack_bf2(hh[0], hh[1]), pack_bf2(hh[2], hh[3])};
        uint32_t lu[2] = {pack_bf2(ll[0], ll[1]), pack_bf2(ll[2], ll[3])};
        *(uint2*)(qc + qdst) = *(uint2*)hu;
        *(uint2*)(qc + S + qdst) = *(uint2*)lu;
    }
    {
        float a[4] = {k.x, k.y, k.z, k.w};
        __nv_bfloat16 hh[4], ll[4];
        #pragma unroll
        for (int j = 0; j < 4; j++) split_bf(a[j], hh[j], ll[j]);
        uint32_t hu[2] = {pack_bf2(hh[0], hh[1]), pack_bf2(hh[2], hh[3])};
        uint32_t lu[2] = {pack_bf2(ll[0], ll[1]), pack_bf2(ll[2], ll[3])};
        *(uint2*)(kc + qdst) = *(uint2*)hu;
        *(uint2*)(kc + S + qdst) = *(uint2*)lu;
    }
    {
        float a[4] = {v.x, v.y, v.z, v.w};
        #pragma unroll
        for (int j = 0; j < 4; j++) {
            __nv_bfloat16 h2, l2; split_bf(a[j], h2, l2);
            long vdst = (bh * DK + d + j) * T + t;
            vc[vdst] = h2; vc[S + vdst] = l2;
        }
    }
}

__global__ void softmax_cat_k(const float* __restrict__ sc, const int* __restrict__ seq,
                              __nv_bfloat16* __restrict__ out, long S) {
    long row = blockIdx.x;
    int b = (int)(row / ((long)NH * T));
    const float* p = sc + row * T;
    const int* sq = seq + (long)b * T;
    const float scale = 0.08838834764831845f;
    int t = threadIdx.x;
    float4 v4 = *(const float4*)(p + t * 4);
    int4 s4 = *(const int4*)(sq + t * 4);
    float vals[4] = {v4.x, v4.y, v4.z, v4.w};
    int ss[4] = {s4.x, s4.y, s4.z, s4.w};
    float mx = -3.0e38f;
    #pragma unroll
    for (int j = 0; j < 4; j++) {
        vals[j] = (ss[j] == 0) ? -3.0e38f : vals[j] * scale;
        mx = fmaxf(mx, vals[j]);
    }
    float M = blockReduceMax(mx);
    float s = 0.f;
    #pragma unroll
    for (int j = 0; j < 4; j++) { vals[j] = __expf(vals[j] - M); s += vals[j]; }
    float Ssum = blockReduceSum(s);
    float inv = 1.f / Ssum;
    __nv_bfloat16 hh[4], ll[4];
    #pragma unroll
    for (int j = 0; j < 4; j++) split_bf(vals[j] * inv, hh[j], ll[j]);
    uint32_t hu[2] = {pack_bf2(hh[0], hh[1]), pack_bf2(hh[2], hh[3])};
    uint32_t lu[2] = {pack_bf2(ll[0], ll[1]), pack_bf2(ll[2], ll[3])};
    long ob = row * T + t * 4;
    *(uint2*)(out + ob) = *(uint2*)hu;
    *(uint2*)(out + S + ob) = *(uint2*)lu;
}

__global__ void copy_np_k(float* __restrict__ out) {
    int i = blockIdx.x * blockDim.x + threadIdx.x;
    if (i < M_ALL) out[i] = g_nonpad[i];
}

// ---------------- HMMA split-bf16 GEMM (mma.sync m16n8k16) ----------------
// C[m,n] = sum_k A[m,k]*B[n,k], split precision (hi*hi + lo*hi + hi*lo).
// Tile 128x128, 8 warps (4x2), warp tile 32x64, K-chunk 32, double-buffered.
constexpr int TG_STRIDE = 40;                       // bf16 elems per smem row (pad)
constexpr int TG_PLANE  = 128 * TG_STRIDE;          // elems per plane
constexpr int TG_BUF    = 2 * TG_PLANE;             // hi+lo planes per buffer
constexpr int TG_SMEM   = (int)(4 * TG_BUF * sizeof(__nv_bfloat16));  // A+B, 2 bufs = 81920B

__global__ void __launch_bounds__(256, 1)
tgemm(const __nv_bfloat16* __restrict__ A, int lda, long Sa, long aSb, long aSh,
      const __nv_bfloat16* __restrict__ B, int ldb, long Sb, long bSb, long bSh,
      float* __restrict__ Cf, __nv_bfloat16* __restrict__ Chi, long Sc,
      int ldc, long cSb, long cSh,
      int K, int H,
      const float* __restrict__ bias, const float* __restrict__ resid,
      const float* __restrict__ mask, int relu) {
    extern __shared__ __nv_bfloat16 smem[];
    __nv_bfloat16* As = smem;                // [2 buf][2 plane][128][40]
    __nv_bfloat16* Bs = smem + 2 * TG_BUF;

    int tid = threadIdx.x, wid = tid >> 5, lane = tid & 31;
    int warp_m = wid & 3, warp_n = wid >> 2;

    int z = blockIdx.z, zb = z / H, zh = z - zb * H;
    A += (long)zb * aSb + (long)zh * aSh;
    B += (long)zb * bSb + (long)zh * bSh;
    long cOff = (long)zb * cSb + (long)zh * cSh;
    if (Cf)    Cf += cOff;
    if (Chi)   Chi += cOff;
    if (resid) resid += cOff;
    int m0 = blockIdx.x * 128, n0 = blockIdx.y * 128;

    // load indices: 256 threads, each loads 8 bf16 (uint4) per plane per half
    int lr = tid >> 2;            // 0..63 (row, +64 second iter)
    int lc = (tid & 3) * 8;       // col within 32-elem chunk

    float acc[2][8][4];
    #pragma unroll
    for (int a = 0; a < 2; a++)
        #pragma unroll
        for (int b = 0; b < 8; b++)
            #pragma unroll
            for (int c = 0; c < 4; c++) acc[a][b][c] = 0.f;

    // prologue: chunk 0 -> buffer 0
    #pragma unroll
    for (int j = 0; j < 2; j++) {
        int r = lr + j * 64;
        long ak = (long)(m0 + r) * lda + lc;
        long bk = (long)(n0 + r) * ldb + lc;
        *(uint4*)&As[r * TG_STRIDE + lc]            = *(const uint4*)(A + ak);
        *(uint4*)&As[TG_PLANE + r * TG_STRIDE + lc] = *(const uint4*)(A + Sa + ak);
        *(uint4*)&Bs[r * TG_STRIDE + lc]            = *(const uint4*)(B + bk);
        *(uint4*)&Bs[TG_PLANE + r * TG_STRIDE + lc] = *(const uint4*)(B + Sb + bk);
    }
    __syncthreads();

    int nc = K >> 5;
    int buf = 0;
    for (int i = 0; i < nc; i++) {
        bool more = (i + 1) < nc;
        uint4 sa[2], sal[2], sb2[2], sbl[2];
        if (more) {
            int k0 = (i + 1) << 5;
            #pragma unroll
            for (int j = 0; j < 2; j++) {
                int r = lr + j * 64;
                long ak = (long)(m0 + r) * lda + k0 + lc;
                long bk = (long)(n0 + r) * ldb + k0 + lc;
                sa[j]  = *(const uint4*)(A + ak);
                sal[j] = *(const uint4*)(A + Sa + ak);
                sb2[j] = *(const uint4*)(B + bk);
                sbl[j] = *(const uint4*)(B + Sb + bk);
            }
        }

        // compute current buffer
        const __nv_bfloat16* Ab = As + buf * TG_BUF;
        const __nv_bfloat16* Bb = Bs + buf * TG_BUF;
        #pragma unroll
        for (int ks = 0; ks < 2; ks++) {
            uint32_t ah[2][4], al[2][4];
            #pragma unroll
            for (int mt = 0; mt < 2; mt++) {
                int row = warp_m * 32 + mt * 16 + (lane & 15);
                int col = ks * 16 + ((lane >> 4) << 3);
                uint32_t ad = smem_u32(Ab + row * TG_STRIDE + col);
                ldm4(ah[mt], ad);
                ldm4(al[mt], ad + TG_PLANE * 2);
            }
            #pragma unroll
            for (int tp = 0; tp < 4; tp++) {
                int row = warp_n * 64 + tp * 16 + ((lane >> 4) << 3) + (lane & 7);
                int col = ks * 16 + (((lane >> 3) & 1) << 3);
                uint32_t bd = smem_u32(Bb + row * TG_STRIDE + col);
                uint32_t bh[4], bl[4];
                ldm4(bh, bd);
                ldm4(bl, bd + TG_PLANE * 2);
                #pragma unroll
                for (int mt = 0; mt < 2; mt++) {
                    #pragma unroll
                    for (int nt = 0; nt < 2; nt++) {
                        float* c = acc[mt][tp * 2 + nt];
                        mma16816(c, ah[mt], bh + nt * 2);
                        mma16816(c, al[mt], bh + nt * 2);
                        mma16816(c, ah[mt], bl + nt * 2);
                    }
                }
            }
        }

        if (more) {
            int nb = buf ^ 1;
            __nv_bfloat16* An = As + nb * TG_BUF;
            __nv_bfloat16* Bn = Bs + nb * TG_BUF;
            #pragma unroll
            for (int j = 0; j < 2; j++) {
                int r = lr + j * 64;
                *(uint4*)&An[r * TG_STRIDE + lc]            = sa[j];
                *(uint4*)&An[TG_PLANE + r * TG_STRIDE + lc] = sal[j];
                *(uint4*)&Bn[r * TG_STRIDE + lc]            = sb2[j];
                *(uint4*)&Bn[TG_PLANE + r * TG_STRIDE + lc] = sbl[j];
            }
            __syncthreads();
            buf = nb;
        }
    }

    // epilogue: direct stores
    #pragma unroll
    for (int mt = 0; mt < 2; mt++) {
        #pragma unroll
        for (int nt8 = 0; nt8 < 8; nt8++) {
            float* c = acc[mt][nt8];
            int row0 = m0 + warp_m * 32 + mt * 16 + (lane >> 2);
            int col  = n0 + warp_n * 64 + nt8 * 8 + (lane & 3) * 2;
            #pragma unroll
            for (int half = 0; half < 2; half++) {
                int m = row0 + half * 8;
                float v0 = c[half * 2], v1 = c[half * 2 + 1];
                if (bias) { v0 += bias[col]; v1 += bias[col + 1]; }
                if (relu) { v0 = fmaxf(v0, 0.f); v1 = fmaxf(v1, 0.f); }
                long co = (long)m * ldc + col;
                if (resid) { v0 += resid[co]; v1 += resid[co + 1]; }
                if (mask) { float mk = mask[m]; v0 *= mk; v1 *= mk; }
                if (Cf) { float2 o; o.x = v0; o.y = v1; *(float2*)(Cf + co) = o; }
                if (Chi) {
                    __nv_bfloat16 h0, l0, h1, l1;
                    split_bf(v0, h0, l0); split_bf(v1, h1, l1);
                    *(uint32_t*)(Chi + co)      = pack_bf2(h0, h1);
                    *(uint32_t*)(Chi + Sc + co) = pack_bf2(l0, l1);
                }
            }
        }
    }
}

// ---------------- host orchestration ----------------
extern "C" void kernel_launch(void* const* d_in, const int* in_sizes, int n_in,
                              void* d_out, int out_size) {
    const int*   src_seq  = (const int*)  d_in[0];
    const int*   src_pos  = (const int*)  d_in[1];
    const float* word_emb = (const float*)d_in[2];
    const float* pos_emb  = (const float*)d_in[3];
    const float* qkv_w    = (const float*)d_in[4];
    const float* qkv_b    = (const float*)d_in[5];
    const float* fc_w     = (const float*)d_in[6];
    const float* fc_b     = (const float*)d_in[7];
    const float* ln1_g    = (const float*)d_in[8];
    const float* ln1_b    = (const float*)d_in[9];
    const float* conv1_w  = (const float*)d_in[10];
    const float* conv1_b  = (const float*)d_in[11];
    const float* conv2_w  = (const float*)d_in[12];
    const float* conv2_b  = (const float*)d_in[13];
    const float* ln2_g    = (const float*)d_in[14];
    const float* ln2_b    = (const float*)d_in[15];

    float* x = (float*)d_out;

    cudaFuncSetAttribute(tgemm, cudaFuncAttributeMaxDynamicSharedMemorySize, TG_SMEM);

    __nv_bfloat16 *p_hcat, *p_qc, *p_kc, *p_vc, *p_pc, *p_aoc, *p_hpc, *p_hidc;
    __nv_bfloat16 *p_wqkv, *p_wfc, *p_w1, *p_w2;
    float *p_qkvf, *p_scf, *p_np;
    cudaGetSymbolAddress((void**)&p_hcat, g_hcat);
    cudaGetSymbolAddress((void**)&p_qkvf, g_qkvf);
    cudaGetSymbolAddress((void**)&p_qc,   g_qc);
    cudaGetSymbolAddress((void**)&p_kc,   g_kc);
    cudaGetSymbolAddress((void**)&p_vc,   g_vc);
    cudaGetSymbolAddress((void**)&p_scf,  g_scf);
    cudaGetSymbolAddress((void**)&p_pc,   g_pc);
    cudaGetSymbolAddress((void**)&p_aoc,  g_aoc);
    cudaGetSymbolAddress((void**)&p_hpc,  g_hpc);
    cudaGetSymbolAddress((void**)&p_hidc, g_hidc);
    cudaGetSymbolAddress((void**)&p_wqkv, g_wqkvc);
    cudaGetSymbolAddress((void**)&p_wfc,  g_wfcc);
    cudaGetSymbolAddress((void**)&p_w1,   g_w1c);
    cudaGetSymbolAddress((void**)&p_w2,   g_w2c);
    cudaGetSymbolAddress((void**)&p_np,   g_nonpad);

    // prep
    zero_halo_k<<<(Bsz * 8 * D) / 256, 256>>>(p_hpc, S_HPC);
    cvt_w_k<<<(int)((S_WQKV + 255) / 256), 256>>>(qkv_w, p_wqkv, S_WQKV, S_WQKV);
    cvt_w_k<<<(int)((S_WFC + 255) / 256), 256>>>(fc_w, p_wfc, S_WFC, S_WFC);
    cvt_w1_k<<<(int)((S_W1 + 255) / 256), 256>>>(conv1_w, p_w1, S_W1);
    cvt_w_k<<<(int)((S_W2 + 255) / 256), 256>>>(conv2_w, p_w2, S_W2, S_W2);
    embed_k<<<M_ALL, D>>>(src_seq, src_pos, word_emb, pos_emb, x);

    for (int l = 0; l < L; l++) {
        // ---- attention ----
        ln_cat_k<<<M_ALL / 8, 256>>>(x, ln1_g + l * D, ln1_b + l * D, p_hcat, S_HCAT, 0);

        tgemm<<<dim3(M_ALL / 128, 6, 1), 256, TG_SMEM>>>(
            p_hcat, D, S_HCAT, 0, 0,
            p_wqkv + (long)l * 3 * D * D, D, S_WQKV, 0, 0,
            p_qkvf, nullptr, 0, 3 * D, 0, 0,
            D, 1, qkv_b + (long)l * 3 * D, nullptr, nullptr, 0);

        cvt_qkv_k<<<(int)(((long)M_ALL * 64 + 255) / 256), 256>>>(p_qkvf, p_qc, p_kc, p_vc, S_QC);

        tgemm<<<dim3(8, 8, BH), 256, TG_SMEM>>>(
            p_qc, DK, S_QC, (long)NH * T * DK, (long)T * DK,
            p_kc, DK, S_QC, (long)NH * T * DK, (long)T * DK,
            p_scf, nullptr, 0, T, (long)NH * T * T, (long)T * T,
            DK, NH, nullptr, nullptr, nullptr, 0);

        softmax_cat_k<<<BH * T, 256>>>(p_scf, src_seq, p_pc, S_PC);

        tgemm<<<dim3(8, 1, BH), 256, TG_SMEM>>>(
            p_pc, T, S_PC, (long)NH * T * T, (long)T * T,
            p_vc, T, S_QC, (long)NH * DK * T, (long)DK * T,
            nullptr, p_aoc, S_AOC, D, (long)T * D, DK,
            T, NH, nullptr, nullptr, nullptr, 0);

        tgemm<<<dim3(M_ALL / 128, 2, 1), 256, TG_SMEM>>>(
            p_aoc, D, S_AOC, 0, 0,
            p_wfc + (long)l * D * D, D, S_WFC, 0, 0,
            x, nullptr, 0, D, 0, 0,
            D, 1, fc_b + (long)l * D, x, p_np, 0);

        // ---- conv FFN ----
        ln_cat_k<<<M_ALL / 8, 256>>>(x, ln2_g + l * D, ln2_b + l * D, p_hpc, S_HPC, 1);

        tgemm<<<dim3(8, 8, Bsz), 256, TG_SMEM>>>(
            p_hpc, D, S_HPC, (long)TPAD * D, 0,
            p_w1 + (long)l * DH * D * 9, D * 9, S_W1, 0, 0,
            nullptr, p_hidc, S_HIDC, DH, (long)T * DH, 0,
            D * 9, 1, conv1_b + (long)l * DH, nullptr, nullptr, 1);

        tgemm<<<dim3(M_ALL / 128, 2, 1), 256, TG_SMEM>>>(
            p_hidc, DH, S_HIDC, 0, 0,
            p_w2 + (long)l * D * DH, DH, S_W2, 0, 0,
            x, nullptr, 0, D, 0, 0,
            DH, 1, conv2_b + (long)l * D, x, p_np, 0);
    }

    if (out_size >= M_ALL * D + M_ALL) {
        copy_np_k<<<M_ALL / 256, 256>>>((float*)d_out + (long)M_ALL * D);
    }
}